// round 15
// baseline (speedup 1.0000x reference)
#include <cuda_runtime.h>
#include <math.h>

// ---------------- problem constants (fixed by setup_inputs) ----------------
#define HDIM 28
#define NTOK 21952          // 28^3
#define C_ 256
#define NR 343              // 7^3 (SR-conv output tokens)
#define H2_ 4               // heads per branch
#define SCALE_F 0.17677669529663687f   // 32^-0.5
#define SCL2E 0.25505654442f           // SCALE_F * log2(e)
#define KSR 16384           // 256*4*4*4 im2col K
#define KZ 64               // split-K chunks for SR conv: one per kernel position
#define NP 768              // packed projection width: q1|q2|kv2|y
#define SPAD 20             // smem row stride (words) for tf32 tiles: conflict-free

// ---------------- scratch (device globals; no allocation) ----------------
__device__ float g_p   [NTOK*NP];     // packed: [0,128)=q1 [128,256)=q2 [256,512)=kv2 [512,768)=y
__device__ float g_lepe[NTOK*C_];
__device__ float g_x1p [KZ*NR*C_];    // split-K partials (22.5 MB)
__device__ float g_x1  [NR*C_];
__device__ float g_kv1 [NR*C_];
__device__ float g_o   [NTOK*C_];
__device__ float g_wp  [NP*C_];       // packed projection weights
__device__ float g_bp  [NP];          // packed bias
__device__ float g_wsr [C_*KSR];      // sr_w transposed: [cout][kpos][cin]

// ---------------- tf32 mma helpers ----------------
__device__ __forceinline__ unsigned f2tf(float f) {
    unsigned u; asm("cvt.rna.tf32.f32 %0,%1;" : "=r"(u) : "f"(f)); return u;
}
__device__ __forceinline__ void mma8(float* c, unsigned a0, unsigned a1, unsigned a2,
                                     unsigned a3, unsigned b0, unsigned b1) {
    asm("mma.sync.aligned.m16n8k8.row.col.f32.tf32.tf32.f32 "
        "{%0,%1,%2,%3},{%4,%5,%6,%7},{%8,%9},{%0,%1,%2,%3};"
        : "+f"(c[0]), "+f"(c[1]), "+f"(c[2]), "+f"(c[3])
        : "r"(a0), "r"(a1), "r"(a2), "r"(a3), "r"(b0), "r"(b1));
}

// ---- FMA-pipe 2^t (no MUFU). Valid |t| < 2^22; rel err ~2e-6. ----
__device__ __forceinline__ float exp2f_fma(float t) {
    float z = t + 12582912.0f;            // round-to-nearest via magic number
    float r = z - 12582912.0f;
    float f = t - r;                      // f in [-0.5, 0.5]
    int   e = __float_as_int(z) - 0x4B400000;
    float p = 1.33333562e-3f;
    p = fmaf(p, f, 9.61812910e-3f);
    p = fmaf(p, f, 5.55041087e-2f);
    p = fmaf(p, f, 2.40226507e-1f);
    p = fmaf(p, f, 6.93147181e-1f);
    p = fmaf(p, f, 1.0f);
    return p * __int_as_float((e + 127) << 23);
}

// ---------------- weight packing (q1|q2|kv2|lepe) ----------------
__global__ void pack_w(const float* __restrict__ q1w, const float* __restrict__ q2w,
                       const float* __restrict__ kv2w, const float* __restrict__ lepew,
                       const float* __restrict__ lepeb,
                       float* __restrict__ wp, float* __restrict__ bp) {
    int i = blockIdx.x * 256 + threadIdx.x;
    if (i < NP * C_) {
        int r = i >> 8, c = i & 255;
        float v;
        if (r < 128)      v = q1w[r * C_ + c];
        else if (r < 256) v = q2w[(r - 128) * C_ + c];
        else if (r < 512) v = kv2w[(r - 256) * C_ + c];
        else              v = lepew[(r - 512) * C_ + c];
        wp[i] = v;
    }
    if (i < NP) bp[i] = (i >= 512) ? lepeb[i - 512] : 0.f;
}

// -------- sr weight transpose: w[cout][cin][kpos] -> wsr[cout][kpos][cin] --------
__global__ void pack_wsr(const float* __restrict__ w, float* __restrict__ wsr) {
    __shared__ float t[32][257];
    const int cout = blockIdx.x;
    const int tid = threadIdx.x;
    const float* wr = w + (size_t)cout * KSR + (size_t)tid * 64;
    float* wo = wsr + (size_t)cout * KSR;
#pragma unroll
    for (int half = 0; half < 2; half++) {
#pragma unroll
        for (int j4 = 0; j4 < 8; j4++) {
            float4 v = *(const float4*)(wr + half * 32 + j4 * 4);
            t[j4*4+0][tid] = v.x; t[j4*4+1][tid] = v.y;
            t[j4*4+2][tid] = v.z; t[j4*4+3][tid] = v.w;
        }
        __syncthreads();
#pragma unroll
        for (int j = 0; j < 32; j++)
            wo[(size_t)(half * 32 + j) * C_ + tid] = t[j][tid];
        __syncthreads();
    }
}

// ------------- 128x128 tf32 tensor-core GEMM -------------
__global__ void __launch_bounds__(256, 2)
gemm_tf32(const float* __restrict__ A, const float* __restrict__ A2,
          const float* __restrict__ W, const float* __restrict__ bias,
          float* __restrict__ out, int M, int K, int Nc) {
    __shared__ unsigned As[128][SPAD];
    __shared__ unsigned Ws[128][SPAD];
    const int tid = threadIdx.x;
    const int lane = tid & 31, warp = tid >> 5;
    const int wm = warp & 1, wn = warp >> 1;
    const int qr = lane >> 2, qc = lane & 3;
    const int bm = blockIdx.y << 7, bn = blockIdx.x << 7;

    const int lr = tid >> 1;
    const int lc = (tid & 1) << 3;

    const int am = bm + lr;
    const bool aval = am < M;
    const float* Ap  = A + (size_t)am * K + lc;
    const float* A2p = A2 ? A2 + (size_t)am * K + lc : nullptr;
    const float* Wp  = W + (size_t)(bn + lr) * K + lc;

    float4 a0 = make_float4(0.f,0.f,0.f,0.f), a1 = a0, w0, w1;
    if (aval) {
        a0 = *(const float4*)(Ap);
        a1 = *(const float4*)(Ap + 4);
        if (A2p) {
            float4 b = *(const float4*)(A2p);
            a0.x += b.x; a0.y += b.y; a0.z += b.z; a0.w += b.w;
            b = *(const float4*)(A2p + 4);
            a1.x += b.x; a1.y += b.y; a1.z += b.z; a1.w += b.w;
        }
    }
    w0 = *(const float4*)(Wp);
    w1 = *(const float4*)(Wp + 4);

    float acc[4][4][4];
#pragma unroll
    for (int i = 0; i < 4; i++)
#pragma unroll
        for (int j = 0; j < 4; j++)
#pragma unroll
            for (int q = 0; q < 4; q++) acc[i][j][q] = 0.f;

    for (int k0 = 0; k0 < K; k0 += 16) {
        uint4 ua = make_uint4(f2tf(a0.x), f2tf(a0.y), f2tf(a0.z), f2tf(a0.w));
        uint4 ub = make_uint4(f2tf(a1.x), f2tf(a1.y), f2tf(a1.z), f2tf(a1.w));
        *(uint4*)&As[lr][lc]     = ua;
        *(uint4*)&As[lr][lc + 4] = ub;
        ua = make_uint4(f2tf(w0.x), f2tf(w0.y), f2tf(w0.z), f2tf(w0.w));
        ub = make_uint4(f2tf(w1.x), f2tf(w1.y), f2tf(w1.z), f2tf(w1.w));
        *(uint4*)&Ws[lr][lc]     = ua;
        *(uint4*)&Ws[lr][lc + 4] = ub;
        __syncthreads();

        const int kn = k0 + 16;
        if (kn < K) {
            a0 = make_float4(0.f,0.f,0.f,0.f); a1 = a0;
            if (aval) {
                a0 = *(const float4*)(Ap + kn);
                a1 = *(const float4*)(Ap + kn + 4);
                if (A2p) {
                    float4 b = *(const float4*)(A2p + kn);
                    a0.x += b.x; a0.y += b.y; a0.z += b.z; a0.w += b.w;
                    b = *(const float4*)(A2p + kn + 4);
                    a1.x += b.x; a1.y += b.y; a1.z += b.z; a1.w += b.w;
                }
            }
            w0 = *(const float4*)(Wp + kn);
            w1 = *(const float4*)(Wp + kn + 4);
        }

#pragma unroll
        for (int kk = 0; kk < 16; kk += 8) {
            unsigned af[4][4], bf[4][2];
#pragma unroll
            for (int mt = 0; mt < 4; mt++) {
                int r0 = wm * 64 + mt * 16 + qr;
                af[mt][0] = As[r0][kk + qc];
                af[mt][1] = As[r0 + 8][kk + qc];
                af[mt][2] = As[r0][kk + 4 + qc];
                af[mt][3] = As[r0 + 8][kk + 4 + qc];
            }
#pragma unroll
            for (int nt = 0; nt < 4; nt++) {
                int nb = wn * 32 + nt * 8 + qr;
                bf[nt][0] = Ws[nb][kk + qc];
                bf[nt][1] = Ws[nb][kk + 4 + qc];
            }
#pragma unroll
            for (int mt = 0; mt < 4; mt++)
#pragma unroll
                for (int nt = 0; nt < 4; nt++)
                    mma8(acc[mt][nt], af[mt][0], af[mt][1], af[mt][2], af[mt][3],
                         bf[nt][0], bf[nt][1]);
        }
        __syncthreads();
    }

#pragma unroll
    for (int mt = 0; mt < 4; mt++) {
#pragma unroll
        for (int nt = 0; nt < 4; nt++) {
            int c = bn + wn * 32 + nt * 8 + qc * 2;
            float bb0 = bias ? bias[c] : 0.f;
            float bb1 = bias ? bias[c + 1] : 0.f;
            int r0 = bm + wm * 64 + mt * 16 + qr;
            if (r0 < M)
                *(float2*)(out + (size_t)r0 * Nc + c) =
                    make_float2(acc[mt][nt][0] + bb0, acc[mt][nt][1] + bb1);
            if (r0 + 8 < M)
                *(float2*)(out + (size_t)(r0 + 8) * Nc + c) =
                    make_float2(acc[mt][nt][2] + bb0, acc[mt][nt][3] + bb1);
        }
    }
}

// ---- SR conv split-K tf32 GEMM: one block-z per kernel position ----
__global__ void __launch_bounds__(256, 2)
srconv_tf32(const float* __restrict__ x, const float* __restrict__ wsr,
            float* __restrict__ part) {
    __shared__ unsigned As[128][SPAD];
    __shared__ unsigned Ws[128][SPAD];
    const int tid = threadIdx.x;
    const int lane = tid & 31, warp = tid >> 5;
    const int wm = warp & 1, wn = warp >> 1;
    const int qr = lane >> 2, qc = lane & 3;
    const int bn = blockIdx.x << 7;
    const int bm = blockIdx.y << 7;
    const int kz = blockIdx.z;
    const int kh = kz >> 4, kw = (kz >> 2) & 3, kd = kz & 3;

    const int lr = tid >> 1;
    const int lc = (tid & 1) << 3;

    const int nr = bm + lr;
    const bool aval = nr < NR;
    int tok = 0;
    if (aval) {
        int oh = nr / 49; int r = nr % 49; int ow = r / 7; int od = r % 7;
        tok = ((4 * oh + kh) * HDIM + 4 * ow + kw) * HDIM + 4 * od + kd;
    }
    const float* Ap = x + (size_t)tok * C_ + lc;
    const float* Wp = wsr + (size_t)(bn + lr) * KSR + (size_t)kz * C_ + lc;

    float4 a0 = make_float4(0.f,0.f,0.f,0.f), a1 = a0, w0, w1;
    if (aval) { a0 = *(const float4*)(Ap); a1 = *(const float4*)(Ap + 4); }
    w0 = *(const float4*)(Wp);
    w1 = *(const float4*)(Wp + 4);

    float acc[4][4][4];
#pragma unroll
    for (int i = 0; i < 4; i++)
#pragma unroll
        for (int j = 0; j < 4; j++)
#pragma unroll
            for (int q = 0; q < 4; q++) acc[i][j][q] = 0.f;

    for (int k0 = 0; k0 < C_; k0 += 16) {
        uint4 ua = make_uint4(f2tf(a0.x), f2tf(a0.y), f2tf(a0.z), f2tf(a0.w));
        uint4 ub = make_uint4(f2tf(a1.x), f2tf(a1.y), f2tf(a1.z), f2tf(a1.w));
        *(uint4*)&As[lr][lc]     = ua;
        *(uint4*)&As[lr][lc + 4] = ub;
        ua = make_uint4(f2tf(w0.x), f2tf(w0.y), f2tf(w0.z), f2tf(w0.w));
        ub = make_uint4(f2tf(w1.x), f2tf(w1.y), f2tf(w1.z), f2tf(w1.w));
        *(uint4*)&Ws[lr][lc]     = ua;
        *(uint4*)&Ws[lr][lc + 4] = ub;
        __syncthreads();

        const int kn = k0 + 16;
        if (kn < C_) {
            a0 = make_float4(0.f,0.f,0.f,0.f); a1 = a0;
            if (aval) { a0 = *(const float4*)(Ap + kn); a1 = *(const float4*)(Ap + kn + 4); }
            w0 = *(const float4*)(Wp + kn);
            w1 = *(const float4*)(Wp + kn + 4);
        }

#pragma unroll
        for (int kk = 0; kk < 16; kk += 8) {
            unsigned af[4][4], bf[4][2];
#pragma unroll
            for (int mt = 0; mt < 4; mt++) {
                int r0 = wm * 64 + mt * 16 + qr;
                af[mt][0] = As[r0][kk + qc];
                af[mt][1] = As[r0 + 8][kk + qc];
                af[mt][2] = As[r0][kk + 4 + qc];
                af[mt][3] = As[r0 + 8][kk + 4 + qc];
            }
#pragma unroll
            for (int nt = 0; nt < 4; nt++) {
                int nb = wn * 32 + nt * 8 + qr;
                bf[nt][0] = Ws[nb][kk + qc];
                bf[nt][1] = Ws[nb][kk + 4 + qc];
            }
#pragma unroll
            for (int mt = 0; mt < 4; mt++)
#pragma unroll
                for (int nt = 0; nt < 4; nt++)
                    mma8(acc[mt][nt], af[mt][0], af[mt][1], af[mt][2], af[mt][3],
                         bf[nt][0], bf[nt][1]);
        }
        __syncthreads();
    }

    float* pz = part + (size_t)kz * (NR * C_);
#pragma unroll
    for (int mt = 0; mt < 4; mt++) {
#pragma unroll
        for (int nt = 0; nt < 4; nt++) {
            int c = bn + wn * 32 + nt * 8 + qc * 2;
            int r0 = bm + wm * 64 + mt * 16 + qr;
            if (r0 < NR)
                *(float2*)(pz + (size_t)r0 * C_ + c) =
                    make_float2(acc[mt][nt][0], acc[mt][nt][1]);
            if (r0 + 8 < NR)
                *(float2*)(pz + (size_t)(r0 + 8) * C_ + c) =
                    make_float2(acc[mt][nt][2], acc[mt][nt][3]);
        }
    }
}

__global__ void sr_reduce(float* __restrict__ x1, const float* __restrict__ part) {
    int i4 = blockIdx.x * 256 + threadIdx.x;
    const int n4 = NR * C_ / 4;
    if (i4 < n4) {
        float4 s = make_float4(0.f, 0.f, 0.f, 0.f);
#pragma unroll
        for (int z = 0; z < KZ; z++) {
            float4 v = ((const float4*)part)[(size_t)z * n4 + i4];
            s.x += v.x; s.y += v.y; s.z += v.z; s.w += v.w;
        }
        ((float4*)x1)[i4] = s;
    }
}

// ---------------- depthwise 3x3x3 SAME conv; input = packed y ----------------
__global__ void dwconv3(const float* __restrict__ p, const float* __restrict__ w,
                        const float* __restrict__ b, float* __restrict__ out) {
    const int n = blockIdx.x;
    const int c = threadIdx.x;
    const int d  = n % HDIM;
    const int wv = (n / HDIM) % HDIM;
    const int h  = n / (HDIM * HDIM);

    float wreg[27];
#pragma unroll
    for (int j = 0; j < 27; j++) wreg[j] = w[c * 27 + j];

    float s = b[c];
#pragma unroll
    for (int kh = 0; kh < 3; kh++) {
        int hh = h + kh - 1;
        if (hh < 0 || hh >= HDIM) continue;
#pragma unroll
        for (int kw = 0; kw < 3; kw++) {
            int ww = wv + kw - 1;
            if (ww < 0 || ww >= HDIM) continue;
#pragma unroll
            for (int kd = 0; kd < 3; kd++) {
                int dd = d + kd - 1;
                if (dd < 0 || dd >= HDIM) continue;
                s += wreg[kh * 9 + kw * 3 + kd] *
                     p[(size_t)((hh * HDIM + ww) * HDIM + dd) * NP + 512 + c];
            }
        }
    }
    out[(size_t)n * C_ + c] = s;
}

// ---------------- layernorm (+sr bias) + exact GELU, in place ----------------
__global__ void ln_gelu(float* __restrict__ x1, const float* __restrict__ srb,
                        const float* __restrict__ g, const float* __restrict__ b) {
    __shared__ float red[256];
    const int r = blockIdx.x, c = threadIdx.x;
    float v = x1[(size_t)r * C_ + c] + srb[c];

    red[c] = v; __syncthreads();
    for (int s = 128; s > 0; s >>= 1) { if (c < s) red[c] += red[c + s]; __syncthreads(); }
    float mu = red[0] * (1.f / 256.f);
    __syncthreads();

    float dv = v - mu;
    red[c] = dv * dv; __syncthreads();
    for (int s = 128; s > 0; s >>= 1) { if (c < s) red[c] += red[c + s]; __syncthreads(); }
    float var = red[0] * (1.f / 256.f);

    float xn = dv * rsqrtf(var + 1e-5f) * g[c] + b[c];
    float out = 0.5f * xn * (1.f + erff(xn * 0.70710678118654752f));
    x1[(size_t)r * C_ + c] = out;
}

// ---------------- branch 1: global attention; FMA-pipe exp2 softmax ----------------
#define CH1 176
__global__ void attn_global(const float* __restrict__ p, const float* __restrict__ kv1,
                            float* __restrict__ o) {
    __shared__ float4 sk[CH1][8];
    __shared__ float4 sv[CH1][8];
    const int h = blockIdx.y;
    const int n = blockIdx.x * 256 + threadIdx.x;
    const bool valid = n < NTOK;

    float q[32];
    if (valid) {
        const float4* qp = (const float4*)(p + (size_t)n * NP + h * 32);
#pragma unroll
        for (int i = 0; i < 8; i++) {
            float4 t = qp[i];
            q[4*i] = t.x * SCL2E; q[4*i+1] = t.y * SCL2E;
            q[4*i+2] = t.z * SCL2E; q[4*i+3] = t.w * SCL2E;
        }
    }

    float l = 0.f, acc[32];
#pragma unroll
    for (int i = 0; i < 32; i++) acc[i] = 0.f;

    for (int c0 = 0; c0 < NR; c0 += CH1) {
        const int cn = min(CH1, NR - c0);
        for (int idx = threadIdx.x; idx < cn * 8; idx += 256) {
            int m = idx >> 3, dq = idx & 7;
            sk[m][dq] = *(const float4*)(kv1 + (size_t)(c0 + m) * C_ + h * 32 + dq * 4);
            sv[m][dq] = *(const float4*)(kv1 + (size_t)(c0 + m) * C_ + 128 + h * 32 + dq * 4);
        }
        __syncthreads();
        if (valid) {
            for (int m = 0; m < cn; m++) {
                float s = 0.f;
#pragma unroll
                for (int i = 0; i < 8; i++) {
                    float4 kk = sk[m][i];
                    s += q[4*i] * kk.x + q[4*i+1] * kk.y
                       + q[4*i+2] * kk.z + q[4*i+3] * kk.w;
                }
                float pw = exp2f_fma(s);        // scores already in log2 domain
                l += pw;
#pragma unroll
                for (int i = 0; i < 8; i++) {
                    float4 vv = sv[m][i];
                    acc[4*i]   += pw * vv.x;
                    acc[4*i+1] += pw * vv.y;
                    acc[4*i+2] += pw * vv.z;
                    acc[4*i+3] += pw * vv.w;
                }
            }
        }
        __syncthreads();
    }

    if (valid) {
        float inv = 1.f / l;
        float4* op = (float4*)(o + (size_t)n * C_ + h * 32);
#pragma unroll
        for (int i = 0; i < 8; i++)
            op[i] = make_float4(acc[4*i]*inv, acc[4*i+1]*inv,
                                acc[4*i+2]*inv, acc[4*i+3]*inv);
    }
}

// ---------------- branch 2: 7x7x7 windowed attention; FMA-pipe exp2 ----------------
__global__ void attn_window(const float* __restrict__ p, float* __restrict__ o) {
    __shared__ float4 sk[CH1][8];
    __shared__ float4 sv[CH1][8];
    const int h = blockIdx.y;
    const int w = blockIdx.x;
    const int wh = w >> 4, ww = (w >> 2) & 3, wd = w & 3;
    const int t = threadIdx.x;
    const bool valid = t < NR;

    int n = 0;
    if (valid) {
        int ih = t / 49, r = t % 49, iw = r / 7, id = r % 7;
        n = ((wh * 7 + ih) * HDIM + ww * 7 + iw) * HDIM + wd * 7 + id;
    }

    float q[32];
    if (valid) {
        const float4* qp = (const float4*)(p + (size_t)n * NP + 128 + h * 32);
#pragma unroll
        for (int i = 0; i < 8; i++) {
            float4 tt = qp[i];
            q[4*i] = tt.x * SCL2E; q[4*i+1] = tt.y * SCL2E;
            q[4*i+2] = tt.z * SCL2E; q[4*i+3] = tt.w * SCL2E;
        }
    }

    float l = 0.f, acc[32];
#pragma unroll
    for (int i = 0; i < 32; i++) acc[i] = 0.f;

    for (int c0 = 0; c0 < NR; c0 += CH1) {
        const int cn = min(CH1, NR - c0);
        for (int idx = t; idx < cn * 8; idx += 352) {
            int m = idx >> 3, dq = idx & 7;
            int tm = c0 + m;
            int ih = tm / 49, r = tm % 49, iw = r / 7, id = r % 7;
            int nm = ((wh * 7 + ih) * HDIM + ww * 7 + iw) * HDIM + wd * 7 + id;
            sk[m][dq] = *(const float4*)(p + (size_t)nm * NP + 256 + h * 32 + dq * 4);
            sv[m][dq] = *(const float4*)(p + (size_t)nm * NP + 384 + h * 32 + dq * 4);
        }
        __syncthreads();
        if (valid) {
            for (int m = 0; m < cn; m++) {
                float s = 0.f;
#pragma unroll
                for (int i = 0; i < 8; i++) {
                    float4 kk = sk[m][i];
                    s += q[4*i] * kk.x + q[4*i+1] * kk.y
                       + q[4*i+2] * kk.z + q[4*i+3] * kk.w;
                }
                float pw = exp2f_fma(s);
                l += pw;
#pragma unroll
                for (int i = 0; i < 8; i++) {
                    float4 vv = sv[m][i];
                    acc[4*i]   += pw * vv.x;
                    acc[4*i+1] += pw * vv.y;
                    acc[4*i+2] += pw * vv.z;
                    acc[4*i+3] += pw * vv.w;
                }
            }
        }
        __syncthreads();
    }

    if (valid) {
        float inv = 1.f / l;
        float4* op = (float4*)(o + (size_t)n * C_ + 128 + h * 32);
#pragma unroll
        for (int i = 0; i < 8; i++)
            op[i] = make_float4(acc[4*i]*inv, acc[4*i+1]*inv,
                                acc[4*i+2]*inv, acc[4*i+3]*inv);
    }
}

// ---------------- launch ----------------
extern "C" void kernel_launch(void* const* d_in, const int* in_sizes, int n_in,
                              void* d_out, int out_size) {
    const float* x       = (const float*)d_in[0];
    const float* lepe_w  = (const float*)d_in[4];
    const float* lepe_b  = (const float*)d_in[5];
    const float* lepe_cw = (const float*)d_in[6];
    const float* lepe_cb = (const float*)d_in[7];
    const float* sr_w    = (const float*)d_in[8];
    const float* sr_b    = (const float*)d_in[9];
    const float* norm_g  = (const float*)d_in[10];
    const float* norm_b  = (const float*)d_in[11];
    const float* q1_w    = (const float*)d_in[12];
    const float* kv1_w   = (const float*)d_in[13];
    const float* q2_w    = (const float*)d_in[14];
    const float* kv2_w   = (const float*)d_in[15];
    const float* proj_w  = (const float*)d_in[16];
    const float* proj_b  = (const float*)d_in[17];
    float* out = (float*)d_out;

    float *p, *lepe, *x1p, *x1, *kv1, *o, *wp, *bp, *wsr;
    cudaGetSymbolAddress((void**)&p,    g_p);
    cudaGetSymbolAddress((void**)&lepe, g_lepe);
    cudaGetSymbolAddress((void**)&x1p,  g_x1p);
    cudaGetSymbolAddress((void**)&x1,   g_x1);
    cudaGetSymbolAddress((void**)&kv1,  g_kv1);
    cudaGetSymbolAddress((void**)&o,    g_o);
    cudaGetSymbolAddress((void**)&wp,   g_wp);
    cudaGetSymbolAddress((void**)&bp,   g_bp);
    cudaGetSymbolAddress((void**)&wsr,  g_wsr);

    const int MT = (NTOK + 127) / 128;

    pack_w<<<(NP * C_ + 255) / 256, 256>>>(q1_w, q2_w, kv2_w, lepe_w, lepe_b, wp, bp);
    gemm_tf32<<<dim3(NP / 128, MT), 256>>>(x, nullptr, wp, bp, p, NTOK, C_, NP);

    dwconv3<<<NTOK, C_>>>(p, lepe_cw, lepe_cb, lepe);

    pack_wsr<<<C_, 256>>>(sr_w, wsr);
    srconv_tf32<<<dim3(C_ / 128, (NR + 127) / 128, KZ), 256>>>(x, wsr, x1p);
    sr_reduce<<<(NR * C_ / 4 + 255) / 256, 256>>>(x1, x1p);
    ln_gelu<<<NR, C_>>>(x1, sr_b, norm_g, norm_b);
    gemm_tf32<<<dim3(C_ / 128, (NR + 127) / 128), 256>>>(x1, nullptr, kv1_w, nullptr, kv1, NR, C_, C_);

    attn_global<<<dim3((NTOK + 255) / 256, H2_), 256>>>(p, kv1, o);
    attn_window<<<dim3(64, H2_), 352>>>(p, o);

    gemm_tf32<<<dim3(C_ / 128, MT), 256>>>(o, lepe, proj_w, proj_b, out, NTOK, C_, C_);
}

// round 16
// speedup vs baseline: 1.2512x; 1.2512x over previous
#include <cuda_runtime.h>
#include <math.h>

// ---------------- problem constants (fixed by setup_inputs) ----------------
#define HDIM 28
#define NTOK 21952          // 28^3
#define C_ 256
#define NR 343              // 7^3 (SR-conv output tokens / window size)
#define H2_ 4               // heads per branch
#define SCALE_F 0.17677669529663687f   // 32^-0.5
#define SCL2E 0.25505654442f           // SCALE_F * log2(e)
#define KSR 16384           // 256*4*4*4 im2col K
#define KZ 64               // split-K chunks for SR conv: one per kernel position
#define NP 768              // packed projection width: q1|q2|kv2|y
#define SPAD 20             // smem row stride (words) for tf32 GEMM tiles

// attention smem layout (words)
#define QS_W   (128*36)
#define KS_W   (128*36)
#define VT_W   (40*132)
#define PS_W   (128*132)
#define ATT_SMEM_BYTES ((QS_W + KS_W + VT_W + PS_W) * 4)   // 125568

// ---------------- scratch (device globals; no allocation) ----------------
__device__ float g_p   [NTOK*NP];     // packed: [0,128)=q1 [128,256)=q2 [256,512)=kv2 [512,768)=y
__device__ float g_lepe[NTOK*C_];
__device__ float g_x1p [KZ*NR*C_];    // split-K partials
__device__ float g_x1  [NR*C_];
__device__ float g_kv1 [NR*C_];
__device__ float g_o   [NTOK*C_];
__device__ float g_wp  [NP*C_];       // packed projection weights
__device__ float g_bp  [NP];          // packed bias
__device__ float g_wsr [C_*KSR];      // sr_w transposed: [cout][kpos][cin]

// ---------------- tf32 mma helpers ----------------
__device__ __forceinline__ unsigned f2tf(float f) {
    unsigned u; asm("cvt.rna.tf32.f32 %0,%1;" : "=r"(u) : "f"(f)); return u;
}
__device__ __forceinline__ void mma8(float* c, unsigned a0, unsigned a1, unsigned a2,
                                     unsigned a3, unsigned b0, unsigned b1) {
    asm("mma.sync.aligned.m16n8k8.row.col.f32.tf32.tf32.f32 "
        "{%0,%1,%2,%3},{%4,%5,%6,%7},{%8,%9},{%0,%1,%2,%3};"
        : "+f"(c[0]), "+f"(c[1]), "+f"(c[2]), "+f"(c[3])
        : "r"(a0), "r"(a1), "r"(a2), "r"(a3), "r"(b0), "r"(b1));
}

// ---- FMA-pipe 2^t (no MUFU). Valid |t| < 2^22; rel err ~2e-6. ----
__device__ __forceinline__ float exp2f_fma(float t) {
    float z = t + 12582912.0f;
    float r = z - 12582912.0f;
    float f = t - r;
    int   e = __float_as_int(z) - 0x4B400000;
    float p = 1.33333562e-3f;
    p = fmaf(p, f, 9.61812910e-3f);
    p = fmaf(p, f, 5.55041087e-2f);
    p = fmaf(p, f, 2.40226507e-1f);
    p = fmaf(p, f, 6.93147181e-1f);
    p = fmaf(p, f, 1.0f);
    return p * __int_as_float((e + 127) << 23);
}

__device__ __forceinline__ int winmap(int wh, int ww, int wd, int t) {
    int ih = t / 49, r = t % 49, iw = r / 7, id = r % 7;
    return ((wh * 7 + ih) * HDIM + ww * 7 + iw) * HDIM + wd * 7 + id;
}

// ---------------- weight packing (q1|q2|kv2|lepe) ----------------
__global__ void pack_w(const float* __restrict__ q1w, const float* __restrict__ q2w,
                       const float* __restrict__ kv2w, const float* __restrict__ lepew,
                       const float* __restrict__ lepeb,
                       float* __restrict__ wp, float* __restrict__ bp) {
    int i = blockIdx.x * 256 + threadIdx.x;
    if (i < NP * C_) {
        int r = i >> 8, c = i & 255;
        float v;
        if (r < 128)      v = q1w[r * C_ + c];
        else if (r < 256) v = q2w[(r - 128) * C_ + c];
        else if (r < 512) v = kv2w[(r - 256) * C_ + c];
        else              v = lepew[(r - 512) * C_ + c];
        wp[i] = v;
    }
    if (i < NP) bp[i] = (i >= 512) ? lepeb[i - 512] : 0.f;
}

// -------- sr weight transpose: w[cout][cin][kpos] -> wsr[cout][kpos][cin] --------
__global__ void pack_wsr(const float* __restrict__ w, float* __restrict__ wsr) {
    __shared__ float t[32][257];
    const int cout = blockIdx.x;
    const int tid = threadIdx.x;
    const float* wr = w + (size_t)cout * KSR + (size_t)tid * 64;
    float* wo = wsr + (size_t)cout * KSR;
#pragma unroll
    for (int half = 0; half < 2; half++) {
#pragma unroll
        for (int j4 = 0; j4 < 8; j4++) {
            float4 v = *(const float4*)(wr + half * 32 + j4 * 4);
            t[j4*4+0][tid] = v.x; t[j4*4+1][tid] = v.y;
            t[j4*4+2][tid] = v.z; t[j4*4+3][tid] = v.w;
        }
        __syncthreads();
#pragma unroll
        for (int j = 0; j < 32; j++)
            wo[(size_t)(half * 32 + j) * C_ + tid] = t[j][tid];
        __syncthreads();
    }
}

// ------------- 128x128 tf32 tensor-core GEMM -------------
__global__ void __launch_bounds__(256, 2)
gemm_tf32(const float* __restrict__ A, const float* __restrict__ A2,
          const float* __restrict__ W, const float* __restrict__ bias,
          float* __restrict__ out, int M, int K, int Nc) {
    __shared__ unsigned As[128][SPAD];
    __shared__ unsigned Ws[128][SPAD];
    const int tid = threadIdx.x;
    const int lane = tid & 31, warp = tid >> 5;
    const int wm = warp & 1, wn = warp >> 1;
    const int qr = lane >> 2, qc = lane & 3;
    const int bm = blockIdx.y << 7, bn = blockIdx.x << 7;

    const int lr = tid >> 1;
    const int lc = (tid & 1) << 3;

    const int am = bm + lr;
    const bool aval = am < M;
    const float* Ap  = A + (size_t)am * K + lc;
    const float* A2p = A2 ? A2 + (size_t)am * K + lc : nullptr;
    const float* Wp  = W + (size_t)(bn + lr) * K + lc;

    float4 a0 = make_float4(0.f,0.f,0.f,0.f), a1 = a0, w0, w1;
    if (aval) {
        a0 = *(const float4*)(Ap);
        a1 = *(const float4*)(Ap + 4);
        if (A2p) {
            float4 b = *(const float4*)(A2p);
            a0.x += b.x; a0.y += b.y; a0.z += b.z; a0.w += b.w;
            b = *(const float4*)(A2p + 4);
            a1.x += b.x; a1.y += b.y; a1.z += b.z; a1.w += b.w;
        }
    }
    w0 = *(const float4*)(Wp);
    w1 = *(const float4*)(Wp + 4);

    float acc[4][4][4];
#pragma unroll
    for (int i = 0; i < 4; i++)
#pragma unroll
        for (int j = 0; j < 4; j++)
#pragma unroll
            for (int q = 0; q < 4; q++) acc[i][j][q] = 0.f;

    for (int k0 = 0; k0 < K; k0 += 16) {
        uint4 ua = make_uint4(f2tf(a0.x), f2tf(a0.y), f2tf(a0.z), f2tf(a0.w));
        uint4 ub = make_uint4(f2tf(a1.x), f2tf(a1.y), f2tf(a1.z), f2tf(a1.w));
        *(uint4*)&As[lr][lc]     = ua;
        *(uint4*)&As[lr][lc + 4] = ub;
        ua = make_uint4(f2tf(w0.x), f2tf(w0.y), f2tf(w0.z), f2tf(w0.w));
        ub = make_uint4(f2tf(w1.x), f2tf(w1.y), f2tf(w1.z), f2tf(w1.w));
        *(uint4*)&Ws[lr][lc]     = ua;
        *(uint4*)&Ws[lr][lc + 4] = ub;
        __syncthreads();

        const int kn = k0 + 16;
        if (kn < K) {
            a0 = make_float4(0.f,0.f,0.f,0.f); a1 = a0;
            if (aval) {
                a0 = *(const float4*)(Ap + kn);
                a1 = *(const float4*)(Ap + kn + 4);
                if (A2p) {
                    float4 b = *(const float4*)(A2p + kn);
                    a0.x += b.x; a0.y += b.y; a0.z += b.z; a0.w += b.w;
                    b = *(const float4*)(A2p + kn + 4);
                    a1.x += b.x; a1.y += b.y; a1.z += b.z; a1.w += b.w;
                }
            }
            w0 = *(const float4*)(Wp + kn);
            w1 = *(const float4*)(Wp + kn + 4);
        }

#pragma unroll
        for (int kk = 0; kk < 16; kk += 8) {
            unsigned af[4][4], bf[4][2];
#pragma unroll
            for (int mt = 0; mt < 4; mt++) {
                int r0 = wm * 64 + mt * 16 + qr;
                af[mt][0] = As[r0][kk + qc];
                af[mt][1] = As[r0 + 8][kk + qc];
                af[mt][2] = As[r0][kk + 4 + qc];
                af[mt][3] = As[r0 + 8][kk + 4 + qc];
            }
#pragma unroll
            for (int nt = 0; nt < 4; nt++) {
                int nb = wn * 32 + nt * 8 + qr;
                bf[nt][0] = Ws[nb][kk + qc];
                bf[nt][1] = Ws[nb][kk + 4 + qc];
            }
#pragma unroll
            for (int mt = 0; mt < 4; mt++)
#pragma unroll
                for (int nt = 0; nt < 4; nt++)
                    mma8(acc[mt][nt], af[mt][0], af[mt][1], af[mt][2], af[mt][3],
                         bf[nt][0], bf[nt][1]);
        }
        __syncthreads();
    }

#pragma unroll
    for (int mt = 0; mt < 4; mt++) {
#pragma unroll
        for (int nt = 0; nt < 4; nt++) {
            int c = bn + wn * 32 + nt * 8 + qc * 2;
            float bb0 = bias ? bias[c] : 0.f;
            float bb1 = bias ? bias[c + 1] : 0.f;
            int r0 = bm + wm * 64 + mt * 16 + qr;
            if (r0 < M)
                *(float2*)(out + (size_t)r0 * Nc + c) =
                    make_float2(acc[mt][nt][0] + bb0, acc[mt][nt][1] + bb1);
            if (r0 + 8 < M)
                *(float2*)(out + (size_t)(r0 + 8) * Nc + c) =
                    make_float2(acc[mt][nt][2] + bb0, acc[mt][nt][3] + bb1);
        }
    }
}

// ---- SR conv split-K tf32 GEMM: one block-z per kernel position ----
__global__ void __launch_bounds__(256, 2)
srconv_tf32(const float* __restrict__ x, const float* __restrict__ wsr,
            float* __restrict__ part) {
    __shared__ unsigned As[128][SPAD];
    __shared__ unsigned Ws[128][SPAD];
    const int tid = threadIdx.x;
    const int lane = tid & 31, warp = tid >> 5;
    const int wm = warp & 1, wn = warp >> 1;
    const int qr = lane >> 2, qc = lane & 3;
    const int bn = blockIdx.x << 7;
    const int bm = blockIdx.y << 7;
    const int kz = blockIdx.z;
    const int kh = kz >> 4, kw = (kz >> 2) & 3, kd = kz & 3;

    const int lr = tid >> 1;
    const int lc = (tid & 1) << 3;

    const int nr = bm + lr;
    const bool aval = nr < NR;
    int tok = 0;
    if (aval) {
        int oh = nr / 49; int r = nr % 49; int ow = r / 7; int od = r % 7;
        tok = ((4 * oh + kh) * HDIM + 4 * ow + kw) * HDIM + 4 * od + kd;
    }
    const float* Ap = x + (size_t)tok * C_ + lc;
    const float* Wp = wsr + (size_t)(bn + lr) * KSR + (size_t)kz * C_ + lc;

    float4 a0 = make_float4(0.f,0.f,0.f,0.f), a1 = a0, w0, w1;
    if (aval) { a0 = *(const float4*)(Ap); a1 = *(const float4*)(Ap + 4); }
    w0 = *(const float4*)(Wp);
    w1 = *(const float4*)(Wp + 4);

    float acc[4][4][4];
#pragma unroll
    for (int i = 0; i < 4; i++)
#pragma unroll
        for (int j = 0; j < 4; j++)
#pragma unroll
            for (int q = 0; q < 4; q++) acc[i][j][q] = 0.f;

    for (int k0 = 0; k0 < C_; k0 += 16) {
        uint4 ua = make_uint4(f2tf(a0.x), f2tf(a0.y), f2tf(a0.z), f2tf(a0.w));
        uint4 ub = make_uint4(f2tf(a1.x), f2tf(a1.y), f2tf(a1.z), f2tf(a1.w));
        *(uint4*)&As[lr][lc]     = ua;
        *(uint4*)&As[lr][lc + 4] = ub;
        ua = make_uint4(f2tf(w0.x), f2tf(w0.y), f2tf(w0.z), f2tf(w0.w));
        ub = make_uint4(f2tf(w1.x), f2tf(w1.y), f2tf(w1.z), f2tf(w1.w));
        *(uint4*)&Ws[lr][lc]     = ua;
        *(uint4*)&Ws[lr][lc + 4] = ub;
        __syncthreads();

        const int kn = k0 + 16;
        if (kn < C_) {
            a0 = make_float4(0.f,0.f,0.f,0.f); a1 = a0;
            if (aval) { a0 = *(const float4*)(Ap + kn); a1 = *(const float4*)(Ap + kn + 4); }
            w0 = *(const float4*)(Wp + kn);
            w1 = *(const float4*)(Wp + kn + 4);
        }

#pragma unroll
        for (int kk = 0; kk < 16; kk += 8) {
            unsigned af[4][4], bf[4][2];
#pragma unroll
            for (int mt = 0; mt < 4; mt++) {
                int r0 = wm * 64 + mt * 16 + qr;
                af[mt][0] = As[r0][kk + qc];
                af[mt][1] = As[r0 + 8][kk + qc];
                af[mt][2] = As[r0][kk + 4 + qc];
                af[mt][3] = As[r0 + 8][kk + 4 + qc];
            }
#pragma unroll
            for (int nt = 0; nt < 4; nt++) {
                int nb = wn * 32 + nt * 8 + qr;
                bf[nt][0] = Ws[nb][kk + qc];
                bf[nt][1] = Ws[nb][kk + 4 + qc];
            }
#pragma unroll
            for (int mt = 0; mt < 4; mt++)
#pragma unroll
                for (int nt = 0; nt < 4; nt++)
                    mma8(acc[mt][nt], af[mt][0], af[mt][1], af[mt][2], af[mt][3],
                         bf[nt][0], bf[nt][1]);
        }
        __syncthreads();
    }

    float* pz = part + (size_t)kz * (NR * C_);
#pragma unroll
    for (int mt = 0; mt < 4; mt++) {
#pragma unroll
        for (int nt = 0; nt < 4; nt++) {
            int c = bn + wn * 32 + nt * 8 + qc * 2;
            int r0 = bm + wm * 64 + mt * 16 + qr;
            if (r0 < NR)
                *(float2*)(pz + (size_t)r0 * C_ + c) =
                    make_float2(acc[mt][nt][0], acc[mt][nt][1]);
            if (r0 + 8 < NR)
                *(float2*)(pz + (size_t)(r0 + 8) * C_ + c) =
                    make_float2(acc[mt][nt][2], acc[mt][nt][3]);
        }
    }
}

__global__ void sr_reduce(float* __restrict__ x1, const float* __restrict__ part) {
    int i4 = blockIdx.x * 256 + threadIdx.x;
    const int n4 = NR * C_ / 4;
    if (i4 < n4) {
        float4 s = make_float4(0.f, 0.f, 0.f, 0.f);
#pragma unroll
        for (int z = 0; z < KZ; z++) {
            float4 v = ((const float4*)part)[(size_t)z * n4 + i4];
            s.x += v.x; s.y += v.y; s.z += v.z; s.w += v.w;
        }
        ((float4*)x1)[i4] = s;
    }
}

// ---------------- depthwise 3x3x3 SAME conv; input = packed y ----------------
__global__ void dwconv3(const float* __restrict__ p, const float* __restrict__ w,
                        const float* __restrict__ b, float* __restrict__ out) {
    const int n = blockIdx.x;
    const int c = threadIdx.x;
    const int d  = n % HDIM;
    const int wv = (n / HDIM) % HDIM;
    const int h  = n / (HDIM * HDIM);

    float wreg[27];
#pragma unroll
    for (int j = 0; j < 27; j++) wreg[j] = w[c * 27 + j];

    float s = b[c];
#pragma unroll
    for (int kh = 0; kh < 3; kh++) {
        int hh = h + kh - 1;
        if (hh < 0 || hh >= HDIM) continue;
#pragma unroll
        for (int kw = 0; kw < 3; kw++) {
            int ww = wv + kw - 1;
            if (ww < 0 || ww >= HDIM) continue;
#pragma unroll
            for (int kd = 0; kd < 3; kd++) {
                int dd = d + kd - 1;
                if (dd < 0 || dd >= HDIM) continue;
                s += wreg[kh * 9 + kw * 3 + kd] *
                     p[(size_t)((hh * HDIM + ww) * HDIM + dd) * NP + 512 + c];
            }
        }
    }
    out[(size_t)n * C_ + c] = s;
}

// ---------------- layernorm (+sr bias) + exact GELU, in place ----------------
__global__ void ln_gelu(float* __restrict__ x1, const float* __restrict__ srb,
                        const float* __restrict__ g, const float* __restrict__ b) {
    __shared__ float red[256];
    const int r = blockIdx.x, c = threadIdx.x;
    float v = x1[(size_t)r * C_ + c] + srb[c];

    red[c] = v; __syncthreads();
    for (int s = 128; s > 0; s >>= 1) { if (c < s) red[c] += red[c + s]; __syncthreads(); }
    float mu = red[0] * (1.f / 256.f);
    __syncthreads();

    float dv = v - mu;
    red[c] = dv * dv; __syncthreads();
    for (int s = 128; s > 0; s >>= 1) { if (c < s) red[c] += red[c + s]; __syncthreads(); }
    float var = red[0] * (1.f / 256.f);

    float xn = dv * rsqrtf(var + 1e-5f) * g[c] + b[c];
    float out = 0.5f * xn * (1.f + erff(xn * 0.70710678118654752f));
    x1[(size_t)r * C_ + c] = out;
}

// ================= tensor-core flash attention =================
// WIN=0: global branch. grid (172, 4): x=qtile, y=head. Q from g_p[.. h*32],
//        K/V from kv1[NR][256]. Output cols h*32.
// WIN=1: windowed.      grid (3, 64, 4): x=qtile, y=window, z=head. Q/K/V from
//        g_p offsets 128/256/384. Output cols 128+h*32.
// Per block: 128 queries x 1 head. Keys in 3 chunks of 128 (last masked).
// S=Q K^T via tf32 mma, exp (log2e folded into Q), P->smem tf32, O += P V^T
// with V^T extended by a ones row so column 32 of O is the softmax denominator.
template<int WIN>
__global__ void __launch_bounds__(256, 1)
attn_tc(const float* __restrict__ p, const float* __restrict__ kv1,
        float* __restrict__ o) {
    extern __shared__ unsigned sm[];
    unsigned* Qs = sm;                 // [128][36]
    unsigned* Ks = Qs + QS_W;          // [128][36]
    unsigned* VT = Ks + KS_W;          // [40][132]  rows 0..31 = V^T, 32 = ones
    unsigned* Ps = VT + VT_W;          // [128][132]

    const int tid = threadIdx.x;
    const int lane = tid & 31, warp = tid >> 5;
    const int qr = lane >> 2, qc = lane & 3;
    const int wm = warp & 1, wn = warp >> 1;
    const int qt = blockIdx.x;
    const int head = WIN ? blockIdx.z : blockIdx.y;
    int wh = 0, ww = 0, wd = 0;
    if (WIN) { int w = blockIdx.y; wh = w >> 4; ww = (w >> 2) & 3; wd = w & 3; }

    // ---- stage Q (scaled by SCALE*log2(e), tf32) ----
    {
        int lr = tid >> 1, lc = (tid & 1) << 4;
        int row = qt * 128 + lr;
        bool v = WIN ? (row < NR) : (row < NTOK);
        const float* src = nullptr;
        if (v) {
            int n = WIN ? winmap(wh, ww, wd, row) : row;
            src = p + (size_t)n * NP + (WIN ? 128 : 0) + head * 32 + lc;
        }
        unsigned* q = Qs + lr * 36 + lc;
#pragma unroll
        for (int j = 0; j < 4; j++) {
            float4 t4 = v ? *(const float4*)(src + j * 4) : make_float4(0,0,0,0);
            *(uint4*)(q + j * 4) = make_uint4(f2tf(t4.x * SCL2E), f2tf(t4.y * SCL2E),
                                              f2tf(t4.z * SCL2E), f2tf(t4.w * SCL2E));
        }
    }

    float Oa[5][4];
#pragma unroll
    for (int i = 0; i < 5; i++)
#pragma unroll
        for (int j = 0; j < 4; j++) Oa[i][j] = 0.f;

    for (int ch = 0; ch < 3; ch++) {
        const int kb = ch * 128;

        // ---- stage K chunk ----
        {
            int lr = tid >> 1, lc = (tid & 1) << 4;
            int key = kb + lr;
            bool v = key < NR;
            const float* src = nullptr;
            if (v) {
                int n = WIN ? winmap(wh, ww, wd, key) : key;
                src = WIN ? p + (size_t)n * NP + 256 + head * 32 + lc
                          : kv1 + (size_t)n * C_ + head * 32 + lc;
            }
            unsigned* kd2 = Ks + lr * 36 + lc;
#pragma unroll
            for (int j = 0; j < 4; j++) {
                float4 t4 = v ? *(const float4*)(src + j * 4) : make_float4(0,0,0,0);
                *(uint4*)(kd2 + j * 4) = make_uint4(f2tf(t4.x), f2tf(t4.y),
                                                    f2tf(t4.z), f2tf(t4.w));
            }
        }
        // ---- stage V^T chunk (+ ones row 32, zero rows 33..39) ----
        if (tid < 128) {
            int key = kb + tid;
            bool v = key < NR;
            const float* src = nullptr;
            if (v) {
                int n = WIN ? winmap(wh, ww, wd, key) : key;
                src = WIN ? p + (size_t)n * NP + 384 + head * 32
                          : kv1 + (size_t)n * C_ + 128 + head * 32;
            }
#pragma unroll
            for (int j = 0; j < 8; j++) {
                float4 t4 = v ? *(const float4*)(src + j * 4) : make_float4(0,0,0,0);
                VT[(4*j+0) * 132 + tid] = f2tf(t4.x);
                VT[(4*j+1) * 132 + tid] = f2tf(t4.y);
                VT[(4*j+2) * 132 + tid] = f2tf(t4.z);
                VT[(4*j+3) * 132 + tid] = f2tf(t4.w);
            }
            VT[32 * 132 + tid] = v ? 0x3F800000u : 0u;
        } else {
            int t2 = tid - 128;
#pragma unroll
            for (int j = 0; j < 7; j++) VT[(33 + j) * 132 + t2] = 0u;
        }
        __syncthreads();

        // ---- S = Q K^T (128x128, k=32) ----
        float acc[4][4][4];
#pragma unroll
        for (int i = 0; i < 4; i++)
#pragma unroll
            for (int j = 0; j < 4; j++)
#pragma unroll
                for (int q = 0; q < 4; q++) acc[i][j][q] = 0.f;

#pragma unroll
        for (int kk = 0; kk < 32; kk += 8) {
            unsigned af[4][4], bf[4][2];
#pragma unroll
            for (int mt = 0; mt < 4; mt++) {
                int r0 = wm * 64 + mt * 16 + qr;
                af[mt][0] = Qs[r0 * 36 + kk + qc];
                af[mt][1] = Qs[(r0 + 8) * 36 + kk + qc];
                af[mt][2] = Qs[r0 * 36 + kk + 4 + qc];
                af[mt][3] = Qs[(r0 + 8) * 36 + kk + 4 + qc];
            }
#pragma unroll
            for (int nt = 0; nt < 4; nt++) {
                int nb = wn * 32 + nt * 8 + qr;
                bf[nt][0] = Ks[nb * 36 + kk + qc];
                bf[nt][1] = Ks[nb * 36 + kk + 4 + qc];
            }
#pragma unroll
            for (int mt = 0; mt < 4; mt++)
#pragma unroll
                for (int nt = 0; nt < 4; nt++)
                    mma8(acc[mt][nt], af[mt][0], af[mt][1], af[mt][2], af[mt][3],
                         bf[nt][0], bf[nt][1]);
        }

        // ---- P = exp2(S) with key masking; write tf32 to Ps ----
        const bool full = (kb + 128 <= NR);
#pragma unroll
        for (int mt = 0; mt < 4; mt++) {
            int r0 = wm * 64 + mt * 16 + qr;
#pragma unroll
            for (int nt = 0; nt < 4; nt++) {
                int cb = wn * 32 + nt * 8 + 2 * qc;
                bool v0 = full || (kb + cb < NR);
                bool v1 = full || (kb + cb + 1 < NR);
                float p00 = v0 ? exp2f_fma(acc[mt][nt][0]) : 0.f;
                float p01 = v1 ? exp2f_fma(acc[mt][nt][1]) : 0.f;
                float p10 = v0 ? exp2f_fma(acc[mt][nt][2]) : 0.f;
                float p11 = v1 ? exp2f_fma(acc[mt][nt][3]) : 0.f;
                *(uint2*)(Ps + r0 * 132 + cb)       = make_uint2(f2tf(p00), f2tf(p01));
                *(uint2*)(Ps + (r0 + 8) * 132 + cb) = make_uint2(f2tf(p10), f2tf(p11));
            }
        }
        __syncthreads();

        // ---- O += P V^T : each warp 16 rows x 40 cols, k=128 ----
#pragma unroll
        for (int kk = 0; kk < 128; kk += 8) {
            unsigned a0 = Ps[(16 * warp + qr) * 132 + kk + qc];
            unsigned a1 = Ps[(16 * warp + 8 + qr) * 132 + kk + qc];
            unsigned a2 = Ps[(16 * warp + qr) * 132 + kk + 4 + qc];
            unsigned a3 = Ps[(16 * warp + 8 + qr) * 132 + kk + 4 + qc];
#pragma unroll
            for (int nt = 0; nt < 5; nt++) {
                unsigned b0 = VT[(nt * 8 + qr) * 132 + kk + qc];
                unsigned b1 = VT[(nt * 8 + qr) * 132 + kk + 4 + qc];
                mma8(Oa[nt], a0, a1, a2, a3, b0, b1);
            }
        }
        __syncthreads();
    }

    // ---- normalize (l = O col 32) and store ----
    float l0 = __shfl_sync(0xffffffffu, Oa[4][0], lane & 28);
    float l1 = __shfl_sync(0xffffffffu, Oa[4][2], lane & 28);
    float i0 = 1.f / l0, i1 = 1.f / l1;

    int r0 = qt * 128 + 16 * warp + qr;
    int r1 = r0 + 8;
    const int cofs = (WIN ? 128 : 0) + head * 32;
    if (WIN ? (r0 < NR) : (r0 < NTOK)) {
        int n0 = WIN ? winmap(wh, ww, wd, r0) : r0;
        float* dst = o + (size_t)n0 * C_ + cofs;
#pragma unroll
        for (int nt = 0; nt < 4; nt++)
            *(float2*)(dst + nt * 8 + 2 * qc) = make_float2(Oa[nt][0] * i0, Oa[nt][1] * i0);
    }
    if (WIN ? (r1 < NR) : (r1 < NTOK)) {
        int n1 = WIN ? winmap(wh, ww, wd, r1) : r1;
        float* dst = o + (size_t)n1 * C_ + cofs;
#pragma unroll
        for (int nt = 0; nt < 4; nt++)
            *(float2*)(dst + nt * 8 + 2 * qc) = make_float2(Oa[nt][2] * i1, Oa[nt][3] * i1);
    }
}

// ---------------- launch ----------------
extern "C" void kernel_launch(void* const* d_in, const int* in_sizes, int n_in,
                              void* d_out, int out_size) {
    const float* x       = (const float*)d_in[0];
    const float* lepe_w  = (const float*)d_in[4];
    const float* lepe_b  = (const float*)d_in[5];
    const float* lepe_cw = (const float*)d_in[6];
    const float* lepe_cb = (const float*)d_in[7];
    const float* sr_w    = (const float*)d_in[8];
    const float* sr_b    = (const float*)d_in[9];
    const float* norm_g  = (const float*)d_in[10];
    const float* norm_b  = (const float*)d_in[11];
    const float* q1_w    = (const float*)d_in[12];
    const float* kv1_w   = (const float*)d_in[13];
    const float* q2_w    = (const float*)d_in[14];
    const float* kv2_w   = (const float*)d_in[15];
    const float* proj_w  = (const float*)d_in[16];
    const float* proj_b  = (const float*)d_in[17];
    float* out = (float*)d_out;

    float *p, *lepe, *x1p, *x1, *kv1, *o, *wp, *bp, *wsr;
    cudaGetSymbolAddress((void**)&p,    g_p);
    cudaGetSymbolAddress((void**)&lepe, g_lepe);
    cudaGetSymbolAddress((void**)&x1p,  g_x1p);
    cudaGetSymbolAddress((void**)&x1,   g_x1);
    cudaGetSymbolAddress((void**)&kv1,  g_kv1);
    cudaGetSymbolAddress((void**)&o,    g_o);
    cudaGetSymbolAddress((void**)&wp,   g_wp);
    cudaGetSymbolAddress((void**)&bp,   g_bp);
    cudaGetSymbolAddress((void**)&wsr,  g_wsr);

    cudaFuncSetAttribute(attn_tc<0>, cudaFuncAttributeMaxDynamicSharedMemorySize,
                         ATT_SMEM_BYTES);
    cudaFuncSetAttribute(attn_tc<1>, cudaFuncAttributeMaxDynamicSharedMemorySize,
                         ATT_SMEM_BYTES);

    const int MT = (NTOK + 127) / 128;   // 172

    pack_w<<<(NP * C_ + 255) / 256, 256>>>(q1_w, q2_w, kv2_w, lepe_w, lepe_b, wp, bp);
    gemm_tf32<<<dim3(NP / 128, MT), 256>>>(x, nullptr, wp, bp, p, NTOK, C_, NP);

    dwconv3<<<NTOK, C_>>>(p, lepe_cw, lepe_cb, lepe);

    pack_wsr<<<C_, 256>>>(sr_w, wsr);
    srconv_tf32<<<dim3(C_ / 128, (NR + 127) / 128, KZ), 256>>>(x, wsr, x1p);
    sr_reduce<<<(NR * C_ / 4 + 255) / 256, 256>>>(x1, x1p);
    ln_gelu<<<NR, C_>>>(x1, sr_b, norm_g, norm_b);
    gemm_tf32<<<dim3(C_ / 128, (NR + 127) / 128), 256>>>(x1, nullptr, kv1_w, nullptr,
                                                         kv1, NR, C_, C_);

    // tensor-core attention -> g_o (cols 0..127 branch1, 128..255 branch2)
    attn_tc<0><<<dim3(MT, H2_), 256, ATT_SMEM_BYTES>>>(p, kv1, o);
    attn_tc<1><<<dim3(3, 64, H2_), 256, ATT_SMEM_BYTES>>>(p, nullptr, o);

    gemm_tf32<<<dim3(C_ / 128, MT), 256>>>(o, lepe, proj_w, proj_b, out, NTOK, C_, C_);
}